// round 7
// baseline (speedup 1.0000x reference)
#include <cuda_runtime.h>

#define NL    64
#define HH    50
#define G4    200
#define DIN   60
#define BATCH 32
#define TT    2048
#define DOUT  50
#define BS    16
#define NSL   2
#define RINGN 16
#define TPB   224

// ---- scratch (device globals). All h/x payloads stored DUPLICATED {v,v} ----
__device__ float d_ring[(NL - 1) * RINGN * HH * 64];   // [layer][slot][u][64] (2 slices x 16b dup)
__device__ int   d_prog[NSL * NL];
__device__ int   d_cons[NSL * NL];
__device__ float d_xT[TT * DIN * 64];                  // [t][d][64]
__device__ float d_hT[TT * HH * 64];                   // [t][u][64]

// lstm smem layout (floats; all offsets 16B-aligned)
#define OFF_WIH 0        // [60][200] k-major
#define OFF_WHH 12000    // [50][200] k-major
#define OFF_B   22000    // [200]
#define OFF_XS  22208    // [60][32] dup'd
#define OFF_HS  24128    // [50][32] dup'd
#define OFF_GS  25728    // [16][200]
#define SMEM_FLOATS 28928
// fc smem layout
#define FOFF_W  0        // [50][50]
#define FOFF_B  2500
#define FOFF_H  2560     // [50][32] dup'd
#define FC_SMEM 4160

__device__ __forceinline__ float sigf(float x) {
    return __fdividef(1.0f, 1.0f + __expf(-x));
}
__device__ __forceinline__ float tanhfast(float x) {
    return 1.0f - __fdividef(2.0f, __expf(2.0f * x) + 1.0f);
}
__device__ __forceinline__ void fma2(unsigned long long& d, unsigned long long a,
                                     unsigned long long b) {
    asm("fma.rn.f32x2 %0, %1, %2, %0;" : "+l"(d) : "l"(a), "l"(b));
}
__device__ __forceinline__ void unpack2(unsigned long long v, float& lo, float& hi) {
    asm("mov.b64 {%0, %1}, %2;" : "=f"(lo), "=f"(hi) : "l"(v));
}
__device__ __forceinline__ int ld_acquire_gpu(const int* p) {
    int v;
    asm volatile("ld.acquire.gpu.global.b32 %0, [%1];" : "=r"(v) : "l"(p) : "memory");
    return v;
}
__device__ __forceinline__ void st_release_gpu(int* p, int v) {
    asm volatile("st.release.gpu.global.b32 [%0], %1;" :: "l"(p), "r"(v) : "memory");
}

__global__ void xpose_kernel(const float* __restrict__ x) {
    if (blockIdx.x == 0 && threadIdx.x < NSL * NL) {
        d_prog[threadIdx.x] = 0;
        d_cons[threadIdx.x] = 0;
    }
    int idx = blockIdx.x * blockDim.x + threadIdx.x;  // (b*DIN+d)*T + t
    if (idx >= BATCH * DIN * TT) return;
    int t = idx % TT;
    int bd = idx / TT;
    int d = bd % DIN, b = bd / DIN;
    float v = x[idx];
    float* dst = d_xT + ((size_t)t * DIN + d) * 64 + b * 2;
    dst[0] = v; dst[1] = v;
}

__global__ void __launch_bounds__(TPB, 1) lstm_kernel(
    const float* __restrict__ hn,  const float* __restrict__ cn,
    const float* __restrict__ Wih0, const float* __restrict__ Wih,
    const float* __restrict__ Whh, const float* __restrict__ bih,
    const float* __restrict__ bhh, const float* __restrict__ fcw,
    const float* __restrict__ fcb, float* __restrict__ out, int has_state)
{
    extern __shared__ float sm[];
    const int tid  = threadIdx.x;
    const int lane = tid & 31;

    // ================= FC consumer role (blocks 128,129) =================
    if (blockIdx.x >= NL * NSL) {
        const int s = blockIdx.x - NL * NSL;
        float* sm_w  = sm + FOFF_W;
        float* sm_fb = sm + FOFF_B;
        float* sm_h  = sm + FOFF_H;
        for (int i = tid; i < DOUT * HH; i += TPB) sm_w[i] = fcw[i];
        for (int i = tid; i < DOUT; i += TPB)      sm_fb[i] = fcb[i];
        __syncthreads();
        const int* prog63 = &d_prog[s * NL + NL - 1];
        for (int t = 0; t < TT; ++t) {
            if (lane == 0) { while (ld_acquire_gpu(prog63) < t + 1) __nanosleep(128); }
            __syncwarp();
            for (int idx = tid; idx < HH * 8; idx += TPB) {   // 32 dup floats per u
                int u = idx >> 3, q = idx & 7;
                float4 v = __ldcg((const float4*)(d_hT + ((size_t)t * HH + u) * 64 + s * 32 + q * 4));
                *(float4*)(sm_h + u * 32 + q * 4) = v;
            }
            __syncthreads();
            if (tid < G4) {
                const int o  = tid % DOUT;
                const int bq = tid / DOUT;
#pragma unroll
                for (int i = 0; i < 4; ++i) {
                    int b = bq * 4 + i;
                    float acc = sm_fb[o];
#pragma unroll 5
                    for (int u = 0; u < HH; ++u)
                        acc = fmaf(sm_h[u * 32 + b * 2], sm_w[o * HH + u], acc);
                    out[((size_t)(s * BS + b) * DOUT + o) * TT + t] = sigf(acc);
                }
            }
            __syncthreads();
        }
        return;
    }

    // ========================= LSTM layer role =========================
    const int layer = blockIdx.x >> 1;
    const int s     = blockIdx.x & 1;
    const int b0    = s * BS;
    const int K1    = (layer == 0) ? DIN : HH;

    float* sm_wih = sm + OFF_WIH;
    float* sm_whh = sm + OFF_WHH;
    float* sm_b   = sm + OFF_B;
    float* sm_xs  = sm + OFF_XS;
    float* sm_hs  = sm + OFF_HS;
    float* sm_gs  = sm + OFF_GS;

    {
        const float* wg = (layer == 0) ? Wih0 : (Wih + (size_t)(layer - 1) * G4 * HH);
        for (int idx = tid; idx < K1 * G4; idx += TPB) {
            int k = idx / G4, j = idx % G4;
            sm_wih[idx] = wg[j * K1 + k];
        }
        const float* wh = Whh + (size_t)layer * G4 * HH;
        for (int idx = tid; idx < HH * G4; idx += TPB) {
            int k = idx / G4, j = idx % G4;
            sm_whh[idx] = wh[j * HH + k];
        }
        for (int j = tid; j < G4; j += TPB)
            sm_b[j] = bih[layer * G4 + j] + bhh[layer * G4 + j];
        // h0 dup'd into sm_hs
        for (int idx = tid; idx < BS * HH; idx += TPB) {
            int u = idx / BS, b = idx % BS;
            float v = hn[((size_t)layer * BATCH + b0 + b) * HH + u];
            sm_hs[u * 32 + b * 2] = v;
            sm_hs[u * 32 + b * 2 + 1] = v;
        }
    }
    // c in regs: thread (u = tid%50, bq = tid/50 in 0..3) owns b = bq*4..bq*4+3
    float creg[4];
    const int u_c  = tid % HH;
    const int bq_c = (tid < G4) ? (tid / HH) : 0;
    if (tid < G4) {
#pragma unroll
        for (int i = 0; i < 4; ++i)
            creg[i] = cn[((size_t)layer * BATCH + b0 + bq_c * 4 + i) * HH + u_c];
    }
    // gemm mapping: thread (jp = tid%100, bh = tid/100) -> j0 = jp*2, batches bh*8..bh*8+7
    const int j0_g = (tid % 100) * 2;
    const int bh_g = (tid < 200) ? (tid / 100) : 0;
    __syncthreads();

    int* prog_prev = (layer > 0)      ? &d_prog[s * NL + layer - 1] : 0;
    int* cons_next = (layer < NL - 1) ? &d_cons[s * NL + layer + 1] : 0;
    int* prog_me   = &d_prog[s * NL + layer];
    int* cons_me   = &d_cons[s * NL + layer];

    for (int t = 0; t < TT; ++t) {
        unsigned long long acc2[8];   // acc2[i] = gates (j0, j0+1) for batch bh*8+i

        // ---- B1: acc = bias + h @ Whh^T (own h, dup layout, no pack) ----
        if (tid < 200) {
            unsigned long long b2 = *(const unsigned long long*)(sm_b + j0_g);
#pragma unroll
            for (int p = 0; p < 8; ++p) acc2[p] = b2;
#pragma unroll 5
            for (int k = 0; k < HH; ++k) {
                unsigned long long w2 = *(const unsigned long long*)(sm_whh + k * G4 + j0_g);
                const ulonglong2* hp = (const ulonglong2*)(sm_hs + k * 32 + bh_g * 16);
                ulonglong2 q0 = hp[0], q1 = hp[1], q2 = hp[2], q3 = hp[3];
                fma2(acc2[0], q0.x, w2); fma2(acc2[1], q0.y, w2);
                fma2(acc2[2], q1.x, w2); fma2(acc2[3], q1.y, w2);
                fma2(acc2[4], q2.x, w2); fma2(acc2[5], q2.y, w2);
                fma2(acc2[6], q3.x, w2); fma2(acc2[7], q3.y, w2);
            }
        }

        // ---- A: waits (uniform block scope) + stage dup'd x ----
        if (layer > 0) {
            if (lane == 0) { while (ld_acquire_gpu(prog_prev) < t + 1) __nanosleep(32); }
            __syncwarp();
        }
        if (layer < NL - 1 && t >= RINGN) {
            if (lane == 0) { while (ld_acquire_gpu(cons_next) < t - RINGN + 1) __nanosleep(32); }
            __syncwarp();
        }
        if (layer == 0) {
            const float* xp = d_xT + (size_t)t * DIN * 64 + s * 32;
            for (int idx = tid; idx < DIN * 8; idx += TPB) {
                int d = idx >> 3, q = idx & 7;
                float4 v = *(const float4*)(xp + d * 64 + q * 4);
                *(float4*)(sm_xs + d * 32 + q * 4) = v;
            }
        } else {
            const float* rp = d_ring + ((size_t)(layer - 1) * RINGN + (t & (RINGN - 1))) * HH * 64 + s * 32;
            for (int idx = tid; idx < HH * 8; idx += TPB) {
                int u = idx >> 3, q = idx & 7;
                float4 v = __ldcg((const float4*)(rp + u * 64 + q * 4));
                *(float4*)(sm_xs + u * 32 + q * 4) = v;
            }
        }
        __syncthreads();
        if (tid == 0 && layer > 0 && (((t & 3) == 3) || t == TT - 1))
            st_release_gpu(cons_me, t + 1);

        // ---- B2: acc += x @ Wih^T ----
        if (tid < 200) {
#pragma unroll 5
            for (int k = 0; k < K1; ++k) {
                unsigned long long w2 = *(const unsigned long long*)(sm_wih + k * G4 + j0_g);
                const ulonglong2* xp = (const ulonglong2*)(sm_xs + k * 32 + bh_g * 16);
                ulonglong2 q0 = xp[0], q1 = xp[1], q2 = xp[2], q3 = xp[3];
                fma2(acc2[0], q0.x, w2); fma2(acc2[1], q0.y, w2);
                fma2(acc2[2], q1.x, w2); fma2(acc2[3], q1.y, w2);
                fma2(acc2[4], q2.x, w2); fma2(acc2[5], q2.y, w2);
                fma2(acc2[6], q3.x, w2); fma2(acc2[7], q3.y, w2);
            }
#pragma unroll
            for (int p = 0; p < 8; ++p)
                *(unsigned long long*)(sm_gs + (bh_g * 8 + p) * G4 + j0_g) = acc2[p];
        }
        __syncthreads();

        // ---- C: cell update (c in regs), publish dup'd h ----
        if (tid < G4) {
            const int u  = u_c;
            const int bq = bq_c;
            float h4[4];
#pragma unroll
            for (int i = 0; i < 4; ++i) {
                int b = bq * 4 + i;
                float gi = sm_gs[b * G4 + u];
                float gf = sm_gs[b * G4 + 50 + u];
                float gg = sm_gs[b * G4 + 100 + u];
                float go = sm_gs[b * G4 + 150 + u];
                float c = sigf(gf) * creg[i] + sigf(gi) * tanhfast(gg);
                float h = sigf(go) * tanhfast(c);
                creg[i] = c;
                h4[i] = h;
            }
            float4 d0 = make_float4(h4[0], h4[0], h4[1], h4[1]);
            float4 d1 = make_float4(h4[2], h4[2], h4[3], h4[3]);
            *(float4*)(sm_hs + u * 32 + bq * 8)     = d0;
            *(float4*)(sm_hs + u * 32 + bq * 8 + 4) = d1;
            float* dst = (layer < NL - 1)
                ? (d_ring + ((size_t)layer * RINGN + (t & (RINGN - 1))) * HH * 64 + u * 64 + s * 32 + bq * 8)
                : (d_hT + ((size_t)t * HH + u) * 64 + s * 32 + bq * 8);
            __stcg((float4*)dst, d0);
            __stcg((float4*)(dst + 4), d1);
            if (t == TT - 1 && has_state) {
                size_t base = (size_t)BATCH * DOUT * TT;
#pragma unroll
                for (int i = 0; i < 4; ++i) {
                    size_t sidx = ((size_t)layer * BATCH + b0 + bq * 4 + i) * HH + u;
                    out[base + sidx] = h4[i];
                    out[base + (size_t)NL * BATCH * HH + sidx] = creg[i];
                }
            }
        }
        __syncthreads();

        // ---- D: publish progress ----
        if (tid == 0) st_release_gpu(prog_me, t + 1);
    }
}

extern "C" void kernel_launch(void* const* d_in, const int* in_sizes, int n_in,
                              void* d_out, int out_size) {
    const float* x    = (const float*)d_in[0];
    const float* hn   = (const float*)d_in[1];
    const float* cn   = (const float*)d_in[2];
    const float* Wih0 = (const float*)d_in[3];
    const float* Wih  = (const float*)d_in[4];
    const float* Whh  = (const float*)d_in[5];
    const float* bih  = (const float*)d_in[6];
    const float* bhh  = (const float*)d_in[7];
    const float* fcw  = (const float*)d_in[8];
    const float* fcb  = (const float*)d_in[9];
    float* out = (float*)d_out;

    const long long full = (long long)BATCH * DOUT * TT + 2LL * NL * BATCH * HH;
    int has_state = (out_size >= full) ? 1 : 0;

    cudaFuncSetAttribute(lstm_kernel, cudaFuncAttributeMaxDynamicSharedMemorySize,
                         SMEM_FLOATS * sizeof(float));

    xpose_kernel<<<(BATCH * DIN * TT + 255) / 256, 256>>>(x);
    lstm_kernel<<<NL * NSL + NSL, TPB, SMEM_FLOATS * sizeof(float)>>>(
        hn, cn, Wih0, Wih, Whh, bih, bhh, fcw, fcb, out, has_state);
}

// round 8
// speedup vs baseline: 1.4093x; 1.4093x over previous
#include <cuda_runtime.h>

#define NL    64
#define HH    50
#define G4    200
#define DIN   60
#define BATCH 32
#define TT    2048
#define DOUT  50
#define BS    16
#define NSL   2
#define RINGN 16
#define TPB   448   // warps 0-6: h-group (tid 0..223), warps 7-13: x-group (tid 224..447)

// ---- scratch (device globals) ----
__device__ float d_ring[(NL - 1) * RINGN * NSL * HH * BS];  // [l][slot][s][u][16]
__device__ int   d_prog[NSL * NL];
__device__ int   d_cons[NSL * NL];
__device__ float d_xT[TT * NSL * DIN * BS];                 // [t][s][d][16]
__device__ float d_hT[TT * NSL * HH * BS];                  // [t][s][u][16]

// lstm smem (floats)
#define OFF_B   0      // [200] (pad to 208)
#define OFF_XS  208    // [60][16]
#define OFF_HS  1168   // [50][20]  (16 data + 4 pad)
#define OFF_GX  2176   // [8][200][2]  x-partial gates, b-pairs
#define OFF_GH  5376   // [8][200][2]  h-partial gates
#define SMEM_FLOATS 8576
// fc smem
#define FOFF_W  0      // [50][50]
#define FOFF_B  2512   // [50]
#define FOFF_H  2576   // [50][16]

__device__ __forceinline__ float sigf(float x) {
    return __fdividef(1.0f, 1.0f + __expf(-x));
}
__device__ __forceinline__ float tanhfast(float x) {
    return 1.0f - __fdividef(2.0f, __expf(2.0f * x) + 1.0f);
}
__device__ __forceinline__ unsigned long long pack2(float x) {
    unsigned long long r;
    asm("mov.b64 %0, {%1, %1};" : "=l"(r) : "f"(x));
    return r;
}
__device__ __forceinline__ void fma2(unsigned long long& d, unsigned long long a,
                                     unsigned long long b) {
    asm("fma.rn.f32x2 %0, %1, %2, %0;" : "+l"(d) : "l"(a), "l"(b));
}
__device__ __forceinline__ int ld_acquire_gpu(const int* p) {
    int v;
    asm volatile("ld.acquire.gpu.global.b32 %0, [%1];" : "=r"(v) : "l"(p) : "memory");
    return v;
}
__device__ __forceinline__ void st_release_gpu(int* p, int v) {
    asm volatile("st.release.gpu.global.b32 [%0], %1;" :: "l"(p), "r"(v) : "memory");
}

__global__ void xpose_kernel(const float* __restrict__ x) {
    if (blockIdx.x == 0 && threadIdx.x < NSL * NL) {
        d_prog[threadIdx.x] = 0;
        d_cons[threadIdx.x] = 0;
    }
    int idx = blockIdx.x * blockDim.x + threadIdx.x;  // (b*DIN+d)*T + t
    if (idx >= BATCH * DIN * TT) return;
    int t = idx % TT;
    int bd = idx / TT;
    int d = bd % DIN, b = bd / DIN;
    d_xT[(((size_t)t * NSL + b / BS) * DIN + d) * BS + (b % BS)] = x[idx];
}

__global__ void __launch_bounds__(TPB, 1) lstm_kernel(
    const float* __restrict__ hn,  const float* __restrict__ cn,
    const float* __restrict__ Wih0, const float* __restrict__ Wih,
    const float* __restrict__ Whh, const float* __restrict__ bih,
    const float* __restrict__ bhh, const float* __restrict__ fcw,
    const float* __restrict__ fcb, float* __restrict__ out, int has_state)
{
    extern __shared__ float sm[];
    const int tid  = threadIdx.x;
    const int lane = tid & 31;

    // ================= FC consumer role (blocks 128,129) =================
    if (blockIdx.x >= NL * NSL) {
        const int s = blockIdx.x - NL * NSL;
        float* sm_w  = sm + FOFF_W;
        float* sm_fb = sm + FOFF_B;
        float* sm_h  = sm + FOFF_H;
        for (int i = tid; i < DOUT * HH; i += TPB) sm_w[i] = fcw[i];
        for (int i = tid; i < DOUT; i += TPB)      sm_fb[i] = fcb[i];
        __syncthreads();
        const int* prog63 = &d_prog[s * NL + NL - 1];
        for (int t = 0; t < TT; ++t) {
            if (lane == 0) { while (ld_acquire_gpu(prog63) < t + 1) __nanosleep(128); }
            __syncwarp();
            const float* hp = d_hT + ((size_t)t * NSL + s) * HH * BS;
            for (int idx = tid; idx < HH * 4; idx += TPB) {
                float4 v = __ldcg((const float4*)(hp + idx * 4));
                *(float4*)(sm_h + idx * 4) = v;
            }
            __syncthreads();
            if (tid < G4) {
                const int o  = tid % DOUT;
                const int bq = tid / DOUT;
#pragma unroll
                for (int i = 0; i < 4; ++i) {
                    int b = bq * 4 + i;
                    float acc = sm_fb[o];
#pragma unroll 5
                    for (int u = 0; u < HH; ++u)
                        acc = fmaf(sm_h[u * BS + b], sm_w[o * HH + u], acc);
                    out[((size_t)(s * BS + b) * DOUT + o) * TT + t] = sigf(acc);
                }
            }
            __syncthreads();
        }
        return;
    }

    // ========================= LSTM layer role =========================
    const int  layer = blockIdx.x >> 1;
    const int  s     = blockIdx.x & 1;
    const int  b0    = s * BS;
    const int  K1    = (layer == 0) ? DIN : HH;
    const bool isX   = (tid >= 224);
    const int  j     = isX ? (tid - 224) : tid;   // gate row, valid if < 200
    const bool act   = (j < G4);

    float* sm_b  = sm + OFF_B;
    float* sm_xs = sm + OFF_XS;
    float* sm_hs = sm + OFF_HS;
    float* sm_gx = sm + OFF_GX;
    float* sm_gh = sm + OFF_GH;

    // ---- init: zero xs, bias, h0 ----
    for (int i = tid; i < DIN * BS; i += TPB) sm_xs[i] = 0.0f;
    for (int jj = tid; jj < G4; jj += TPB)
        sm_b[jj] = bih[layer * G4 + jj] + bhh[layer * G4 + jj];
    for (int idx = tid; idx < HH * BS; idx += TPB) {
        int u = idx / BS, b = idx % BS;
        sm_hs[u * 20 + b] = hn[((size_t)layer * BATCH + b0 + b) * HH + u];
    }

    // ---- weights into registers (per-thread gate-row column) ----
    float wreg[60];
    if (act) {
        if (isX) {
            const float* wg = (layer == 0) ? Wih0 : (Wih + (size_t)(layer - 1) * G4 * HH);
#pragma unroll
            for (int k = 0; k < 60; ++k)
                wreg[k] = (k < K1) ? wg[j * K1 + k] : 0.0f;
        } else {
            const float* wh = Whh + (size_t)layer * G4 * HH;
#pragma unroll
            for (int k = 0; k < 50; ++k)
                wreg[k] = wh[j * HH + k];
        }
    }

    // ---- cell state in regs: thread owns (u, batches 2*bqg, 2*bqg+1) ----
    float creg[2];
    const int u_c = j % HH;
    const int bqg = (isX ? 4 : 0) + (act ? (j / HH) : 0);   // 0..7
    if (act) {
#pragma unroll
        for (int i = 0; i < 2; ++i)
            creg[i] = cn[((size_t)layer * BATCH + b0 + 2 * bqg + i) * HH + u_c];
    }
    __syncthreads();

    int* prog_prev = (layer > 0)      ? &d_prog[s * NL + layer - 1] : 0;
    int* cons_next = (layer < NL - 1) ? &d_cons[s * NL + layer + 1] : 0;
    int* prog_me   = &d_prog[s * NL + layer];
    int* cons_me   = &d_cons[s * NL + layer];

    for (int t = 0; t < TT; ++t) {
        unsigned long long acc2[8];

        if (!isX) {
            // ---------- h-group: B1 = bias + h @ Whh^T (no wait) ----------
            if (act) {
                unsigned long long b2 = pack2(sm_b[j]);
#pragma unroll
                for (int p = 0; p < 8; ++p) acc2[p] = b2;
#pragma unroll
                for (int k = 0; k < 50; ++k) {
                    unsigned long long w2 = pack2(wreg[k]);
                    const ulonglong2* hp = (const ulonglong2*)(sm_hs + k * 20);
                    ulonglong2 q0 = hp[0], q1 = hp[1], q2 = hp[2], q3 = hp[3];
                    fma2(acc2[0], q0.x, w2); fma2(acc2[1], q0.y, w2);
                    fma2(acc2[2], q1.x, w2); fma2(acc2[3], q1.y, w2);
                    fma2(acc2[4], q2.x, w2); fma2(acc2[5], q2.y, w2);
                    fma2(acc2[6], q3.x, w2); fma2(acc2[7], q3.y, w2);
                }
#pragma unroll
                for (int p = 0; p < 8; ++p)
                    *(unsigned long long*)(sm_gh + ((size_t)(p * G4 + j)) * 2) = acc2[p];
            }
        } else {
            // ---------- x-group: poll, stage x, B2 = x @ Wih^T ----------
            if (layer > 0) {
                if (lane == 0) { while (ld_acquire_gpu(prog_prev) < t + 1) __nanosleep(32); }
                __syncwarp();
            }
            if (layer == 0) {
                const float* xp = d_xT + ((size_t)t * NSL + s) * DIN * BS;
                for (int idx = tid - 224; idx < DIN * 4; idx += 224) {
                    float4 v = *(const float4*)(xp + idx * 4);
                    *(float4*)(sm_xs + idx * 4) = v;
                }
            } else {
                const float* rp = d_ring +
                    (((size_t)(layer - 1) * RINGN + (t & (RINGN - 1))) * NSL + s) * HH * BS;
                for (int idx = tid - 224; idx < HH * 4; idx += 224) {
                    float4 v = __ldcg((const float4*)(rp + idx * 4));
                    *(float4*)(sm_xs + idx * 4) = v;
                }
            }
            asm volatile("bar.sync 1, 224;" ::: "memory");   // x-group only
            if (tid == 224 && layer > 0 && (((t & 3) == 3) || t == TT - 1))
                st_release_gpu(cons_me, t + 1);
            if (act) {
#pragma unroll
                for (int p = 0; p < 8; ++p) acc2[p] = 0ull;
#pragma unroll
                for (int k = 0; k < 60; ++k) {
                    unsigned long long w2 = pack2(wreg[k]);
                    const ulonglong2* xp = (const ulonglong2*)(sm_xs + k * BS);
                    ulonglong2 q0 = xp[0], q1 = xp[1], q2 = xp[2], q3 = xp[3];
                    fma2(acc2[0], q0.x, w2); fma2(acc2[1], q0.y, w2);
                    fma2(acc2[2], q1.x, w2); fma2(acc2[3], q1.y, w2);
                    fma2(acc2[4], q2.x, w2); fma2(acc2[5], q2.y, w2);
                    fma2(acc2[6], q3.x, w2); fma2(acc2[7], q3.y, w2);
                }
#pragma unroll
                for (int p = 0; p < 8; ++p)
                    *(unsigned long long*)(sm_gx + ((size_t)(p * G4 + j)) * 2) = acc2[p];
            }
        }

        // ---- ring backpressure (every warp's lane0; uniform) ----
        if (layer < NL - 1 && t >= RINGN) {
            if (lane == 0) { while (ld_acquire_gpu(cons_next) < t - RINGN + 1) __nanosleep(32); }
            __syncwarp();
        }
        __syncthreads();   // gx, gh complete

        // ---- C: sum partials, cell update, publish h ----
        if (act) {
            float h2[2];
#pragma unroll
            for (int i = 0; i < 2; ++i) {
                int base = (bqg * G4) * 2 + i;
                float gi = sm_gx[base + (u_c) * 2]        + sm_gh[base + (u_c) * 2];
                float gf = sm_gx[base + (50 + u_c) * 2]   + sm_gh[base + (50 + u_c) * 2];
                float gg = sm_gx[base + (100 + u_c) * 2]  + sm_gh[base + (100 + u_c) * 2];
                float go = sm_gx[base + (150 + u_c) * 2]  + sm_gh[base + (150 + u_c) * 2];
                float c = sigf(gf) * creg[i] + sigf(gi) * tanhfast(gg);
                float h = sigf(go) * tanhfast(c);
                creg[i] = c;
                h2[i] = h;
            }
            *(float2*)(sm_hs + u_c * 20 + 2 * bqg) = make_float2(h2[0], h2[1]);
            float* dst = (layer < NL - 1)
                ? (d_ring + (((size_t)layer * RINGN + (t & (RINGN - 1))) * NSL + s) * HH * BS
                   + u_c * BS + 2 * bqg)
                : (d_hT + ((size_t)t * NSL + s) * HH * BS + u_c * BS + 2 * bqg);
            __stcg((float2*)dst, make_float2(h2[0], h2[1]));
            if (t == TT - 1 && has_state) {
                size_t base = (size_t)BATCH * DOUT * TT;
#pragma unroll
                for (int i = 0; i < 2; ++i) {
                    size_t sidx = ((size_t)layer * BATCH + b0 + 2 * bqg + i) * HH + u_c;
                    out[base + sidx] = h2[i];
                    out[base + (size_t)NL * BATCH * HH + sidx] = creg[i];
                }
            }
        }
        __syncthreads();   // h in smem/ring complete

        if (tid == 0) st_release_gpu(prog_me, t + 1);
    }
}

extern "C" void kernel_launch(void* const* d_in, const int* in_sizes, int n_in,
                              void* d_out, int out_size) {
    const float* x    = (const float*)d_in[0];
    const float* hn   = (const float*)d_in[1];
    const float* cn   = (const float*)d_in[2];
    const float* Wih0 = (const float*)d_in[3];
    const float* Wih  = (const float*)d_in[4];
    const float* Whh  = (const float*)d_in[5];
    const float* bih  = (const float*)d_in[6];
    const float* bhh  = (const float*)d_in[7];
    const float* fcw  = (const float*)d_in[8];
    const float* fcb  = (const float*)d_in[9];
    float* out = (float*)d_out;

    const long long full = (long long)BATCH * DOUT * TT + 2LL * NL * BATCH * HH;
    int has_state = (out_size >= full) ? 1 : 0;

    cudaFuncSetAttribute(lstm_kernel, cudaFuncAttributeMaxDynamicSharedMemorySize,
                         SMEM_FLOATS * sizeof(float));

    xpose_kernel<<<(BATCH * DIN * TT + 255) / 256, 256>>>(x);
    lstm_kernel<<<NL * NSL + NSL, TPB, SMEM_FLOATS * sizeof(float)>>>(
        hn, cn, Wih0, Wih, Whh, bih, bhh, fcw, fcb, out, has_state);
}

// round 9
// speedup vs baseline: 1.4363x; 1.0192x over previous
#include <cuda_runtime.h>

#define NL    64
#define HH    50
#define G4    200
#define DIN   60
#define BATCH 32
#define TT    2048
#define DOUT  50
#define BS    16
#define NSL   2
#define RINGN 16
#define TPB   256   // warps 0-3: h-group (tid 0..127), warps 4-7: x-group (tid 128..255)

// ---- scratch (device globals) ----
__device__ float d_ring[(NL - 1) * RINGN * NSL * HH * BS];  // [l][slot][s][u][16]
__device__ int   d_prog[NSL * NL];
__device__ int   d_cons[NSL * NL];
__device__ float d_xT[TT * NSL * DIN * BS];                 // [t][s][d][16]
__device__ float d_hT[TT * NSL * HH * BS];                  // [t][s][u][16]

// lstm smem (floats)
#define OFF_B   0      // [200] pad 208
#define OFF_XS  208    // [60][16]
#define OFF_HS  1168   // [50][20] (16 data + 4 pad)
#define OFF_GX  2176   // [(p,j) -> (p*200+j)*2] 3200 floats
#define OFF_GH  5376   // 3200 floats
#define SMEM_FLOATS 8576
// fc smem
#define FOFF_W  0
#define FOFF_B  2512
#define FOFF_H  2576   // [50][16]

__device__ __forceinline__ float sigf(float x) {
    return __fdividef(1.0f, 1.0f + __expf(-x));
}
__device__ __forceinline__ float tanhfast(float x) {
    return 1.0f - __fdividef(2.0f, __expf(2.0f * x) + 1.0f);
}
__device__ __forceinline__ unsigned long long pack2(float x) {
    unsigned long long r;
    asm("mov.b64 %0, {%1, %1};" : "=l"(r) : "f"(x));
    return r;
}
__device__ __forceinline__ void fma2(unsigned long long& d, unsigned long long a,
                                     unsigned long long b) {
    asm("fma.rn.f32x2 %0, %1, %2, %0;" : "+l"(d) : "l"(a), "l"(b));
}
__device__ __forceinline__ int ld_acquire_gpu(const int* p) {
    int v;
    asm volatile("ld.acquire.gpu.global.b32 %0, [%1];" : "=r"(v) : "l"(p) : "memory");
    return v;
}
__device__ __forceinline__ void st_release_gpu(int* p, int v) {
    asm volatile("st.release.gpu.global.b32 [%0], %1;" :: "l"(p), "r"(v) : "memory");
}

__global__ void xpose_kernel(const float* __restrict__ x) {
    if (blockIdx.x == 0 && threadIdx.x < NSL * NL) {
        d_prog[threadIdx.x] = 0;
        d_cons[threadIdx.x] = 0;
    }
    int idx = blockIdx.x * blockDim.x + threadIdx.x;  // (b*DIN+d)*T + t
    if (idx >= BATCH * DIN * TT) return;
    int t = idx % TT;
    int bd = idx / TT;
    int d = bd % DIN, b = bd / DIN;
    d_xT[(((size_t)t * NSL + b / BS) * DIN + d) * BS + (b % BS)] = x[idx];
}

__global__ void __launch_bounds__(TPB, 1) lstm_kernel(
    const float* __restrict__ hn,  const float* __restrict__ cn,
    const float* __restrict__ Wih0, const float* __restrict__ Wih,
    const float* __restrict__ Whh, const float* __restrict__ bih,
    const float* __restrict__ bhh, const float* __restrict__ fcw,
    const float* __restrict__ fcb, float* __restrict__ out, int has_state)
{
    extern __shared__ float sm[];
    const int tid  = threadIdx.x;
    const int lane = tid & 31;

    // ================= FC consumer role (blocks 128,129) =================
    if (blockIdx.x >= NL * NSL) {
        const int s = blockIdx.x - NL * NSL;
        float* sm_w  = sm + FOFF_W;
        float* sm_fb = sm + FOFF_B;
        float* sm_h  = sm + FOFF_H;
        for (int i = tid; i < DOUT * HH; i += TPB) sm_w[i] = fcw[i];
        for (int i = tid; i < DOUT; i += TPB)      sm_fb[i] = fcb[i];
        __syncthreads();
        const int* prog63 = &d_prog[s * NL + NL - 1];
        for (int t = 0; t < TT; ++t) {
            if (lane == 0) { while (ld_acquire_gpu(prog63) < t + 1) __nanosleep(128); }
            __syncwarp();
            const float* hp = d_hT + ((size_t)t * NSL + s) * HH * BS;
            for (int idx = tid; idx < HH * 4; idx += TPB) {
                float4 v = __ldcg((const float4*)(hp + idx * 4));
                *(float4*)(sm_h + idx * 4) = v;
            }
            __syncthreads();
            if (tid < G4) {
                const int o  = tid % DOUT;
                const int bq = tid / DOUT;
#pragma unroll
                for (int i = 0; i < 4; ++i) {
                    int b = bq * 4 + i;
                    float acc = sm_fb[o];
#pragma unroll 5
                    for (int u = 0; u < HH; ++u)
                        acc = fmaf(sm_h[u * BS + b], sm_w[o * HH + u], acc);
                    out[((size_t)(s * BS + b) * DOUT + o) * TT + t] = sigf(acc);
                }
            }
            __syncthreads();
        }
        return;
    }

    // ========================= LSTM layer role =========================
    const int  layer = blockIdx.x >> 1;
    const int  s     = blockIdx.x & 1;
    const int  b0    = s * BS;
    const int  K1    = (layer == 0) ? DIN : HH;
    const bool isX   = (tid >= 128);
    const int  jp    = isX ? (tid - 128) : tid;  // j-pair index; active if < 100
    const bool act   = (jp < 100);
    const int  j0    = jp * 2;

    float* sm_b  = sm + OFF_B;
    float* sm_xs = sm + OFF_XS;
    float* sm_hs = sm + OFF_HS;
    float* sm_gx = sm + OFF_GX;
    float* sm_gh = sm + OFF_GH;

    // ---- init: zero xs, bias, h0 ----
    for (int i = tid; i < DIN * BS; i += TPB) sm_xs[i] = 0.0f;
    for (int jj = tid; jj < G4; jj += TPB)
        sm_b[jj] = bih[layer * G4 + jj] + bhh[layer * G4 + jj];
    for (int idx = tid; idx < HH * BS; idx += TPB) {
        int u = idx / BS, b = idx % BS;
        sm_hs[u * 20 + b] = hn[((size_t)layer * BATCH + b0 + b) * HH + u];
    }

    // ---- weights into registers: TWO gate-row columns per thread ----
    float wA[60], wB[60];
    if (act) {
        if (isX) {
            const float* wg = (layer == 0) ? Wih0 : (Wih + (size_t)(layer - 1) * G4 * HH);
#pragma unroll
            for (int k = 0; k < 60; ++k) {
                wA[k] = (k < K1) ? wg[j0 * K1 + k] : 0.0f;
                wB[k] = (k < K1) ? wg[(j0 + 1) * K1 + k] : 0.0f;
            }
        } else {
            const float* wh = Whh + (size_t)layer * G4 * HH;
#pragma unroll
            for (int k = 0; k < 50; ++k) {
                wA[k] = wh[j0 * HH + k];
                wB[k] = wh[(j0 + 1) * HH + k];
            }
        }
    }

    // ---- cell state in regs: thread tid<200 owns (u = tid%50, batches 4*bq..) ----
    float creg[4];
    const int u_c  = tid % HH;
    const int bq_c = (tid < G4) ? (tid / HH) : 0;  // 0..3
    if (tid < G4) {
#pragma unroll
        for (int i = 0; i < 4; ++i)
            creg[i] = cn[((size_t)layer * BATCH + b0 + 4 * bq_c + i) * HH + u_c];
    }
    __syncthreads();

    int* prog_prev = (layer > 0)      ? &d_prog[s * NL + layer - 1] : 0;
    int* cons_next = (layer < NL - 1) ? &d_cons[s * NL + layer + 1] : 0;
    int* prog_me   = &d_prog[s * NL + layer];
    int* cons_me   = &d_cons[s * NL + layer];

    for (int t = 0; t < TT; ++t) {
        unsigned long long accA[8], accB[8];

        if (!isX) {
            // ---------- h-group: gh = bias + h @ Whh^T (no wait) ----------
            if (act) {
                unsigned long long bA = pack2(sm_b[j0]);
                unsigned long long bB = pack2(sm_b[j0 + 1]);
#pragma unroll
                for (int p = 0; p < 8; ++p) { accA[p] = bA; accB[p] = bB; }
#pragma unroll
                for (int k = 0; k < 50; ++k) {
                    unsigned long long w0 = pack2(wA[k]);
                    unsigned long long w1 = pack2(wB[k]);
                    const ulonglong2* hp = (const ulonglong2*)(sm_hs + k * 20);
                    ulonglong2 q0 = hp[0], q1 = hp[1], q2 = hp[2], q3 = hp[3];
                    fma2(accA[0], q0.x, w0); fma2(accA[1], q0.y, w0);
                    fma2(accA[2], q1.x, w0); fma2(accA[3], q1.y, w0);
                    fma2(accA[4], q2.x, w0); fma2(accA[5], q2.y, w0);
                    fma2(accA[6], q3.x, w0); fma2(accA[7], q3.y, w0);
                    fma2(accB[0], q0.x, w1); fma2(accB[1], q0.y, w1);
                    fma2(accB[2], q1.x, w1); fma2(accB[3], q1.y, w1);
                    fma2(accB[4], q2.x, w1); fma2(accB[5], q2.y, w1);
                    fma2(accB[6], q3.x, w1); fma2(accB[7], q3.y, w1);
                }
#pragma unroll
                for (int p = 0; p < 8; ++p) {
                    ulonglong2 v; v.x = accA[p]; v.y = accB[p];
                    *(ulonglong2*)(sm_gh + (p * G4 + j0) * 2) = v;
                }
            }
        } else {
            // ---------- x-group: poll, stage x, gx = x @ Wih^T ----------
            if (layer > 0) {
                if (lane == 0) { while (ld_acquire_gpu(prog_prev) < t + 1) __nanosleep(32); }
                __syncwarp();
            }
            if (layer == 0) {
                const float* xp = d_xT + ((size_t)t * NSL + s) * DIN * BS;
                for (int idx = tid - 128; idx < DIN * 4; idx += 128) {
                    float4 v = *(const float4*)(xp + idx * 4);
                    *(float4*)(sm_xs + idx * 4) = v;
                }
            } else {
                const float* rp = d_ring +
                    (((size_t)(layer - 1) * RINGN + (t & (RINGN - 1))) * NSL + s) * HH * BS;
                for (int idx = tid - 128; idx < HH * 4; idx += 128) {
                    float4 v = __ldcg((const float4*)(rp + idx * 4));
                    *(float4*)(sm_xs + idx * 4) = v;
                }
            }
            asm volatile("bar.sync 1, 128;" ::: "memory");   // x-group only
            if (tid == 128 && layer > 0 && (((t & 3) == 3) || t == TT - 1))
                st_release_gpu(cons_me, t + 1);
            if (act) {
#pragma unroll
                for (int p = 0; p < 8; ++p) { accA[p] = 0ull; accB[p] = 0ull; }
#pragma unroll
                for (int k = 0; k < 60; ++k) {
                    unsigned long long w0 = pack2(wA[k]);
                    unsigned long long w1 = pack2(wB[k]);
                    const ulonglong2* xp = (const ulonglong2*)(sm_xs + k * BS);
                    ulonglong2 q0 = xp[0], q1 = xp[1], q2 = xp[2], q3 = xp[3];
                    fma2(accA[0], q0.x, w0); fma2(accA[1], q0.y, w0);
                    fma2(accA[2], q1.x, w0); fma2(accA[3], q1.y, w0);
                    fma2(accA[4], q2.x, w0); fma2(accA[5], q2.y, w0);
                    fma2(accA[6], q3.x, w0); fma2(accA[7], q3.y, w0);
                    fma2(accB[0], q0.x, w1); fma2(accB[1], q0.y, w1);
                    fma2(accB[2], q1.x, w1); fma2(accB[3], q1.y, w1);
                    fma2(accB[4], q2.x, w1); fma2(accB[5], q2.y, w1);
                    fma2(accB[6], q3.x, w1); fma2(accB[7], q3.y, w1);
                }
#pragma unroll
                for (int p = 0; p < 8; ++p) {
                    ulonglong2 v; v.x = accA[p]; v.y = accB[p];
                    *(ulonglong2*)(sm_gx + (p * G4 + j0) * 2) = v;
                }
            }
        }

        // ---- ring backpressure (uniform per warp) ----
        if (layer < NL - 1 && t >= RINGN) {
            if (lane == 0) { while (ld_acquire_gpu(cons_next) < t - RINGN + 1) __nanosleep(32); }
            __syncwarp();
        }
        __syncthreads();   // gx, gh complete

        // ---- C: sum partials, cell update, publish h (threads 0..199) ----
        if (tid < G4) {
            float h4[4];
#pragma unroll
            for (int i = 0; i < 4; ++i) {
                int b   = 4 * bq_c + i;
                int pb  = (b >> 1) * G4 * 2 + (b & 1);
                float gi = sm_gx[pb + (u_c) * 2]       + sm_gh[pb + (u_c) * 2];
                float gf = sm_gx[pb + (50 + u_c) * 2]  + sm_gh[pb + (50 + u_c) * 2];
                float gg = sm_gx[pb + (100 + u_c) * 2] + sm_gh[pb + (100 + u_c) * 2];
                float go = sm_gx[pb + (150 + u_c) * 2] + sm_gh[pb + (150 + u_c) * 2];
                float c = sigf(gf) * creg[i] + sigf(gi) * tanhfast(gg);
                float h = sigf(go) * tanhfast(c);
                creg[i] = c;
                h4[i] = h;
                sm_hs[u_c * 20 + b] = h;
            }
            float4 hv = make_float4(h4[0], h4[1], h4[2], h4[3]);
            float* dst = (layer < NL - 1)
                ? (d_ring + (((size_t)layer * RINGN + (t & (RINGN - 1))) * NSL + s) * HH * BS
                   + u_c * BS + 4 * bq_c)
                : (d_hT + ((size_t)t * NSL + s) * HH * BS + u_c * BS + 4 * bq_c);
            __stcg((float4*)dst, hv);
            if (t == TT - 1 && has_state) {
                size_t base = (size_t)BATCH * DOUT * TT;
#pragma unroll
                for (int i = 0; i < 4; ++i) {
                    size_t sidx = ((size_t)layer * BATCH + b0 + 4 * bq_c + i) * HH + u_c;
                    out[base + sidx] = h4[i];
                    out[base + (size_t)NL * BATCH * HH + sidx] = creg[i];
                }
            }
        }
        __syncthreads();   // h in smem/ring complete

        if (tid == 0) st_release_gpu(prog_me, t + 1);
    }
}

extern "C" void kernel_launch(void* const* d_in, const int* in_sizes, int n_in,
                              void* d_out, int out_size) {
    const float* x    = (const float*)d_in[0];
    const float* hn   = (const float*)d_in[1];
    const float* cn   = (const float*)d_in[2];
    const float* Wih0 = (const float*)d_in[3];
    const float* Wih  = (const float*)d_in[4];
    const float* Whh  = (const float*)d_in[5];
    const float* bih  = (const float*)d_in[6];
    const float* bhh  = (const float*)d_in[7];
    const float* fcw  = (const float*)d_in[8];
    const float* fcb  = (const float*)d_in[9];
    float* out = (float*)d_out;

    const long long full = (long long)BATCH * DOUT * TT + 2LL * NL * BATCH * HH;
    int has_state = (out_size >= full) ? 1 : 0;

    cudaFuncSetAttribute(lstm_kernel, cudaFuncAttributeMaxDynamicSharedMemorySize,
                         SMEM_FLOATS * sizeof(float));

    xpose_kernel<<<(BATCH * DIN * TT + 255) / 256, 256>>>(x);
    lstm_kernel<<<NL * NSL + NSL, TPB, SMEM_FLOATS * sizeof(float)>>>(
        hn, cn, Wih0, Wih, Whh, bih, bhh, fcw, fcb, out, has_state);
}

// round 11
// speedup vs baseline: 1.6335x; 1.1373x over previous
#include <cuda_runtime.h>

#define NL    64
#define HH    50
#define G4    200
#define DIN   60
#define BATCH 32
#define TT    2048
#define DOUT  50
#define BS    16
#define NSL   2
#define RINGN 16
#define TPB   256   // warps 0-3: H-group (tid 0..127), warps 4-7: X-group (tid 128..255)

// ---- scratch (device globals) ----
__device__ float d_ring[(NL - 1) * RINGN * NSL * HH * BS];  // [l][slot][s][u][16]
__device__ int   d_prog[NSL * NL];
__device__ int   d_cons[NSL * NL];
__device__ float d_xT[TT * NSL * DIN * BS];                 // [t][s][d][16]
__device__ float d_hT[TT * NSL * HH * BS];                  // [t][s][u][16]

// lstm smem (floats)
#define OFF_B   0      // [200] pad 208
#define OFF_XS  208    // 2 x [60][16]  (double buffer, 960 each)
#define OFF_HS  2128   // [50][16]
#define OFF_GH  2928   // 3200
#define OFF_GX  6128   // 2 x 3200 (double buffer)
#define SMEM_FLOATS 12528
// fc smem
#define FOFF_W  0
#define FOFF_B  2512
#define FOFF_H  2576   // [50][16]

__device__ __forceinline__ float sigf(float x) {
    return __fdividef(1.0f, 1.0f + __expf(-x));
}
__device__ __forceinline__ float tanhfast(float x) {
    return 1.0f - __fdividef(2.0f, __expf(2.0f * x) + 1.0f);
}
__device__ __forceinline__ unsigned long long pack2(float x) {
    unsigned long long r;
    asm("mov.b64 %0, {%1, %1};" : "=l"(r) : "f"(x));
    return r;
}
__device__ __forceinline__ void fma2(unsigned long long& d, unsigned long long a,
                                     unsigned long long b) {
    asm("fma.rn.f32x2 %0, %1, %2, %0;" : "+l"(d) : "l"(a), "l"(b));
}
__device__ __forceinline__ int ld_acquire_gpu(const int* p) {
    int v;
    asm volatile("ld.acquire.gpu.global.b32 %0, [%1];" : "=r"(v) : "l"(p) : "memory");
    return v;
}
__device__ __forceinline__ void st_release_gpu(int* p, int v) {
    asm volatile("st.release.gpu.global.b32 [%0], %1;" :: "l"(p), "r"(v) : "memory");
}

#define BAR_SYNC(id, n)   asm volatile("bar.sync %0, %1;"   :: "r"(id), "r"(n) : "memory")
#define BAR_ARRIVE(id, n) asm volatile("bar.arrive %0, %1;" :: "r"(id), "r"(n) : "memory")

__global__ void xpose_kernel(const float* __restrict__ x) {
    if (blockIdx.x == 0 && threadIdx.x < NSL * NL) {
        d_prog[threadIdx.x] = 0;
        d_cons[threadIdx.x] = 0;
    }
    int idx = blockIdx.x * blockDim.x + threadIdx.x;  // (b*DIN+d)*T + t
    if (idx >= BATCH * DIN * TT) return;
    int t = idx % TT;
    int bd = idx / TT;
    int d = bd % DIN, b = bd / DIN;
    d_xT[(((size_t)t * NSL + b / BS) * DIN + d) * BS + (b % BS)] = x[idx];
}

__global__ void __launch_bounds__(TPB, 1) lstm_kernel(
    const float* __restrict__ hn,  const float* __restrict__ cn,
    const float* __restrict__ Wih0, const float* __restrict__ Wih,
    const float* __restrict__ Whh, const float* __restrict__ bih,
    const float* __restrict__ bhh, const float* __restrict__ fcw,
    const float* __restrict__ fcb, float* __restrict__ out, int has_state)
{
    extern __shared__ float sm[];
    const int tid  = threadIdx.x;
    const int lane = tid & 31;

    // ================= FC consumer role (blocks 128,129) =================
    if (blockIdx.x >= NL * NSL) {
        const int s = blockIdx.x - NL * NSL;
        float* sm_w  = sm + FOFF_W;
        float* sm_fb = sm + FOFF_B;
        float* sm_h  = sm + FOFF_H;
        for (int i = tid; i < DOUT * HH; i += TPB) sm_w[i] = fcw[i];
        for (int i = tid; i < DOUT; i += TPB)      sm_fb[i] = fcb[i];
        __syncthreads();
        const int* prog63 = &d_prog[s * NL + NL - 1];
        for (int t = 0; t < TT; ++t) {
            if (lane == 0) { while (ld_acquire_gpu(prog63) < t + 1) __nanosleep(128); }
            __syncwarp();
            const float* hp = d_hT + ((size_t)t * NSL + s) * HH * BS;
            for (int idx = tid; idx < HH * 4; idx += TPB) {
                float4 v = __ldcg((const float4*)(hp + idx * 4));
                *(float4*)(sm_h + idx * 4) = v;
            }
            __syncthreads();
            if (tid < G4) {
                const int o  = tid % DOUT;
                const int bq = tid / DOUT;
#pragma unroll
                for (int i = 0; i < 4; ++i) {
                    int b = bq * 4 + i;
                    float acc = sm_fb[o];
#pragma unroll 5
                    for (int u = 0; u < HH; ++u)
                        acc = fmaf(sm_h[u * BS + b], sm_w[o * HH + u], acc);
                    out[((size_t)(s * BS + b) * DOUT + o) * TT + t] = sigf(acc);
                }
            }
            __syncthreads();
        }
        return;
    }

    // ========================= LSTM layer role =========================
    const int  layer = blockIdx.x >> 1;
    const int  s     = blockIdx.x & 1;
    const int  b0    = s * BS;
    const int  K1    = (layer == 0) ? DIN : HH;
    const bool isX   = (tid >= 128);
    const int  jp    = isX ? (tid - 128) : tid;   // j-pair; active if < 100
    const bool act   = (jp < 100);
    const int  j0    = jp * 2;

    float* sm_b  = sm + OFF_B;
    float* sm_hs = sm + OFF_HS;
    float* sm_gh = sm + OFF_GH;

    // ---- init: zero xs (both buffers), bias, h0 ----
    for (int i = tid; i < 2 * DIN * BS; i += TPB) sm[OFF_XS + i] = 0.0f;
    for (int jj = tid; jj < G4; jj += TPB)
        sm_b[jj] = bih[layer * G4 + jj] + bhh[layer * G4 + jj];
    for (int idx = tid; idx < HH * BS; idx += TPB) {
        int u = idx / BS, b = idx % BS;
        sm_hs[u * BS + b] = hn[((size_t)layer * BATCH + b0 + b) * HH + u];
    }

    // ---- weights into regs: two gate-row columns per thread ----
    float wA[60], wB[60];
    if (act) {
        if (isX) {
            const float* wg = (layer == 0) ? Wih0 : (Wih + (size_t)(layer - 1) * G4 * HH);
#pragma unroll
            for (int k = 0; k < 60; ++k) {
                wA[k] = (k < K1) ? wg[j0 * K1 + k] : 0.0f;
                wB[k] = (k < K1) ? wg[(j0 + 1) * K1 + k] : 0.0f;
            }
        } else {
            const float* wh = Whh + (size_t)layer * G4 * HH;
#pragma unroll
            for (int k = 0; k < 50; ++k) {
                wA[k] = wh[j0 * HH + k];
                wB[k] = wh[(j0 + 1) * HH + k];
            }
        }
    }

    // ---- cell state in regs (H-group C threads): tid<100: u, bh -> 8 batches ----
    float creg[8];
    const int u_c  = tid % HH;
    const int bh_c = (tid < 100) ? (tid / HH) : 0;   // 0 or 1
    if (!isX && tid < 100) {
#pragma unroll
        for (int i = 0; i < 8; ++i)
            creg[i] = cn[((size_t)layer * BATCH + b0 + bh_c * 8 + i) * HH + u_c];
    }
    __syncthreads();

    int* prog_prev = (layer > 0)      ? &d_prog[s * NL + layer - 1] : 0;
    int* cons_next = (layer < NL - 1) ? &d_cons[s * NL + layer + 1] : 0;
    int* prog_me   = &d_prog[s * NL + layer];
    int* cons_me   = &d_cons[s * NL + layer];

    if (!isX) {
        // ======================= H-group =======================
        for (int t = 0; t < TT; ++t) {
            // ---- B1: gh = bias + h @ Whh^T ----
            if (act) {
                unsigned long long accA[8], accB[8];
                unsigned long long bA = pack2(sm_b[j0]);
                unsigned long long bB = pack2(sm_b[j0 + 1]);
#pragma unroll
                for (int p = 0; p < 8; ++p) { accA[p] = bA; accB[p] = bB; }
#pragma unroll
                for (int k = 0; k < 50; ++k) {
                    unsigned long long w0 = pack2(wA[k]);
                    unsigned long long w1 = pack2(wB[k]);
                    const ulonglong2* hp = (const ulonglong2*)(sm_hs + k * BS);
                    ulonglong2 q0 = hp[0], q1 = hp[1], q2 = hp[2], q3 = hp[3];
                    fma2(accA[0], q0.x, w0); fma2(accA[1], q0.y, w0);
                    fma2(accA[2], q1.x, w0); fma2(accA[3], q1.y, w0);
                    fma2(accA[4], q2.x, w0); fma2(accA[5], q2.y, w0);
                    fma2(accA[6], q3.x, w0); fma2(accA[7], q3.y, w0);
                    fma2(accB[0], q0.x, w1); fma2(accB[1], q0.y, w1);
                    fma2(accB[2], q1.x, w1); fma2(accB[3], q1.y, w1);
                    fma2(accB[4], q2.x, w1); fma2(accB[5], q2.y, w1);
                    fma2(accB[6], q3.x, w1); fma2(accB[7], q3.y, w1);
                }
#pragma unroll
                for (int p = 0; p < 8; ++p) {
                    ulonglong2 v; v.x = accA[p]; v.y = accB[p];
                    *(ulonglong2*)(sm_gh + (p * G4 + j0) * 2) = v;
                }
            }

            // ---- wait gx(t) ready (parity barrier 2/3) ----
            BAR_SYNC(2 + (t & 1), 256);

            // ---- ring backpressure before C's ring stores (uniform in H) ----
            if (layer < NL - 1 && t >= RINGN) {
                if (lane == 0) { while (ld_acquire_gpu(cons_next) < t - RINGN + 1) __nanosleep(32); }
                __syncwarp();
            }

            // ---- C: gates -> c,h (tid<100; 8 batches each) ----
            if (tid < 100) {
                const float* gx = sm + OFF_GX + (t & 1) * 3200;
                float h8[8];
#pragma unroll
                for (int i = 0; i < 8; ++i) {
                    int b    = bh_c * 8 + i;
                    int base = (b >> 1) * G4 * 2 + (b & 1);
                    float gi = gx[base + u_c * 2]         + sm_gh[base + u_c * 2];
                    float gf = gx[base + (50 + u_c) * 2]  + sm_gh[base + (50 + u_c) * 2];
                    float gg = gx[base + (100 + u_c) * 2] + sm_gh[base + (100 + u_c) * 2];
                    float go = gx[base + (150 + u_c) * 2] + sm_gh[base + (150 + u_c) * 2];
                    float c = sigf(gf) * creg[i] + sigf(gi) * tanhfast(gg);
                    float h = sigf(go) * tanhfast(c);
                    creg[i] = c;
                    h8[i] = h;
                }
                float4 v0 = make_float4(h8[0], h8[1], h8[2], h8[3]);
                float4 v1 = make_float4(h8[4], h8[5], h8[6], h8[7]);
                *(float4*)(sm_hs + u_c * BS + bh_c * 8)     = v0;
                *(float4*)(sm_hs + u_c * BS + bh_c * 8 + 4) = v1;
                float* dst = (layer < NL - 1)
                    ? (d_ring + (((size_t)layer * RINGN + (t & (RINGN - 1))) * NSL + s) * HH * BS
                       + u_c * BS + bh_c * 8)
                    : (d_hT + ((size_t)t * NSL + s) * HH * BS + u_c * BS + bh_c * 8);
                __stcg((float4*)dst, v0);
                __stcg((float4*)(dst + 4), v1);
                if (t == TT - 1 && has_state) {
                    size_t base2 = (size_t)BATCH * DOUT * TT;
#pragma unroll
                    for (int i = 0; i < 8; ++i) {
                        size_t sidx = ((size_t)layer * BATCH + b0 + bh_c * 8 + i) * HH + u_c;
                        out[base2 + sidx] = h8[i];
                        out[base2 + (size_t)NL * BATCH * HH + sidx] = creg[i];
                    }
                }
            }
            BAR_ARRIVE(4 + (t & 1), 256);   // gx[t&1] consumed (parity barrier 4/5)
            BAR_SYNC(6, 128);               // h(t) visible to all H before B1(t+1)
            if (tid == 0) st_release_gpu(prog_me, t + 1);
        }
    } else {
        // ======================= X-group =======================
        for (int t = 0; t < TT; ++t) {
            // gx[t&1] buffer free: pairs with H's arrive at t-2 on same parity
            if (t >= 2) BAR_SYNC(4 + (t & 1), 256);
            if (layer > 0) {
                if (lane == 0) { while (ld_acquire_gpu(prog_prev) < t + 1) __nanosleep(32); }
                __syncwarp();
            }
            float* xbuf = sm + OFF_XS + (t & 1) * (DIN * BS);
            if (layer == 0) {
                const float* xp = d_xT + ((size_t)t * NSL + s) * DIN * BS;
                for (int idx = tid - 128; idx < DIN * 4; idx += 128) {
                    float4 v = *(const float4*)(xp + idx * 4);
                    *(float4*)(xbuf + idx * 4) = v;
                }
            } else {
                const float* rp = d_ring +
                    (((size_t)(layer - 1) * RINGN + (t & (RINGN - 1))) * NSL + s) * HH * BS;
                for (int idx = tid - 128; idx < HH * 4; idx += 128) {
                    float4 v = __ldcg((const float4*)(rp + idx * 4));
                    *(float4*)(xbuf + idx * 4) = v;
                }
            }
            BAR_SYNC(7, 128);                      // x staged (X-group only)
            if (tid == 128 && layer > 0 && (((t & 3) == 3) || t == TT - 1))
                st_release_gpu(cons_me, t + 1);

            if (act) {
                unsigned long long accA[8], accB[8];
#pragma unroll
                for (int p = 0; p < 8; ++p) { accA[p] = 0ull; accB[p] = 0ull; }
#pragma unroll
                for (int k = 0; k < 60; ++k) {
                    unsigned long long w0 = pack2(wA[k]);
                    unsigned long long w1 = pack2(wB[k]);
                    const ulonglong2* xp2 = (const ulonglong2*)(xbuf + k * BS);
                    ulonglong2 q0 = xp2[0], q1 = xp2[1], q2 = xp2[2], q3 = xp2[3];
                    fma2(accA[0], q0.x, w0); fma2(accA[1], q0.y, w0);
                    fma2(accA[2], q1.x, w0); fma2(accA[3], q1.y, w0);
                    fma2(accA[4], q2.x, w0); fma2(accA[5], q2.y, w0);
                    fma2(accA[6], q3.x, w0); fma2(accA[7], q3.y, w0);
                    fma2(accB[0], q0.x, w1); fma2(accB[1], q0.y, w1);
                    fma2(accB[2], q1.x, w1); fma2(accB[3], q1.y, w1);
                    fma2(accB[4], q2.x, w1); fma2(accB[5], q2.y, w1);
                    fma2(accB[6], q3.x, w1); fma2(accB[7], q3.y, w1);
                }
                float* gx = sm + OFF_GX + (t & 1) * 3200;
#pragma unroll
                for (int p = 0; p < 8; ++p) {
                    ulonglong2 v; v.x = accA[p]; v.y = accB[p];
                    *(ulonglong2*)(gx + (p * G4 + j0) * 2) = v;
                }
            }
            BAR_ARRIVE(2 + (t & 1), 256);          // gx(t) ready
        }
    }
}

extern "C" void kernel_launch(void* const* d_in, const int* in_sizes, int n_in,
                              void* d_out, int out_size) {
    const float* x    = (const float*)d_in[0];
    const float* hn   = (const float*)d_in[1];
    const float* cn   = (const float*)d_in[2];
    const float* Wih0 = (const float*)d_in[3];
    const float* Wih  = (const float*)d_in[4];
    const float* Whh  = (const float*)d_in[5];
    const float* bih  = (const float*)d_in[6];
    const float* bhh  = (const float*)d_in[7];
    const float* fcw  = (const float*)d_in[8];
    const float* fcb  = (const float*)d_in[9];
    float* out = (float*)d_out;

    const long long full = (long long)BATCH * DOUT * TT + 2LL * NL * BATCH * HH;
    int has_state = (out_size >= full) ? 1 : 0;

    cudaFuncSetAttribute(lstm_kernel, cudaFuncAttributeMaxDynamicSharedMemorySize,
                         SMEM_FLOATS * sizeof(float));

    xpose_kernel<<<(BATCH * DIN * TT + 255) / 256, 256>>>(x);
    lstm_kernel<<<NL * NSL + NSL, TPB, SMEM_FLOATS * sizeof(float)>>>(
        hn, cn, Wih0, Wih, Whh, bih, bhh, fcw, fcb, out, has_state);
}